// round 12
// baseline (speedup 1.0000x reference)
#include <cuda_runtime.h>
#include <cuda_fp16.h>
#include <math.h>
#include <stdint.h>

// Problem constants
#define BATCH   32
#define CHAN    256
#define HH      56
#define WW      56
#define HWHW    3136
#define NWEIGHT (CHAN*CHAN*9)
#define KDIM    2304
#define MDIM    (BATCH*HWHW)            // 100352

// Padded NHWC int8 activation layout
#define PADW    58
#define XPLANE  (PADW*PADW*CHAN)        // 861184 bytes per image per plane
#define NXPAD   (BATCH*XPLANE)          // 27557888 bytes per plane

// GEMM tiling (int8, 3 fixed-point passes)
#define BM 128
#define BN 128
#define BK 128
#define NCHUNK 54                       // 3 passes * 9 taps * 2 ci-halves
#define STAGES 3
#define RSTRIDE 144                     // 128 + 16 pad bytes per tile row
#define TILE_B  (128*RSTRIDE)           // 18432
#define STG     (2*TILE_B)              // 36864 per stage (A then B)
#define SMEM_REQ (STAGES*STG + 2048)

// ---------------- device scratch ----------------
__device__ __align__(256) int8_t g_x8[3*NXPAD];   // 3 int8 planes (~82.7 MB), borders stay 0
__device__ __align__(256) int8_t g_w8[9*CHAN*CHAN]; // 15*wq as [tap][oc][ci]
__device__ float  g_scale[CHAN];
__device__ float  g_bias[CHAN];
__device__ unsigned g_Tbits;

__device__ __forceinline__ uint32_t smem_u32(const void* p) {
    return (uint32_t)__cvta_generic_to_shared(p);
}

// ---------------- kernel 1: max |tanh(w)| -----------------------------------
__global__ __launch_bounds__(256)
void k_max(const float* __restrict__ w) {
    __shared__ float s[256];
    float m = 0.0f;
    for (int i = blockIdx.x*256 + threadIdx.x; i < NWEIGHT; i += 256*256) {
        float t = (float)tanh((double)w[i]);
        m = fmaxf(m, fabsf(t));
    }
    s[threadIdx.x] = m;
    __syncthreads();
    for (int o = 128; o > 0; o >>= 1) {
        if (threadIdx.x < o) s[threadIdx.x] = fmaxf(s[threadIdx.x], s[threadIdx.x+o]);
        __syncthreads();
    }
    // positive floats: bit pattern is order-isomorphic -> atomicMax on uint is exact
    if (threadIdx.x == 0) atomicMax(&g_Tbits, __float_as_uint(s[0]));
}

// ---------------- kernel 2: weight quantize -> int8 [tap][oc][ci] + BN fold -
__global__ void k_prep_w(const float* __restrict__ w,
                         const float* __restrict__ gamma, const float* __restrict__ beta,
                         const float* __restrict__ mean,  const float* __restrict__ var) {
    int e = blockIdx.x*256 + threadIdx.x;      // grid KDIM x 256 == NWEIGHT
    float T = __uint_as_float(g_Tbits);
    float t  = (float)tanh((double)w[e]);
    float tq = __fdiv_rn(t, 2.0f*T) + 0.5f;
    float r  = rintf(tq * 15.0f);              // half-even, matches jnp.round
    int oc = e / KDIM;
    int rr = e - oc*KDIM;
    int ci = rr / 9;
    int tap = rr - ci*9;
    g_w8[(tap*CHAN + oc)*CHAN + ci] = (int8_t)(int)(2.0f*r - 15.0f);

    if (blockIdx.x == 0) {
        int c = threadIdx.x;
        float inv = __fdiv_rn(gamma[c], __fsqrt_rn(var[c] + 1e-5f));
        g_scale[c] = __fdiv_rn(inv, 15.0f);
        g_bias[c]  = fmaf(-mean[c], inv, beta[c]);
    }
}

// ---------------- kernel 3: NCHW fp32 -> 3 padded NHWC int8 planes ----------
__global__ __launch_bounds__(128)
void k_convert(const float* __restrict__ x) {
    __shared__ int8_t sh[3][56][144];          // 24.2 KB, 16B-aligned rows
    int bid = blockIdx.x;
    int cihalf = bid & 1;
    int bh = bid >> 1;
    int h = bh % HH;
    int b = bh / HH;
    int t = threadIdx.x;

    const float* xp = x + ((size_t)(b*CHAN + cihalf*128)*HH + h)*WW;
    #pragma unroll
    for (int i = 0; i < 14; i++) {
        int f = i*128 + t;                     // 128 ci x 14 float4
        int ci = f / 14;
        int c4 = f - ci*14;
        float4 v = *reinterpret_cast<const float4*>(xp + (size_t)ci*HWHW + c4*4);
        int w4 = c4*4;
        float vv[4] = {v.x, v.y, v.z, v.w};
        #pragma unroll
        for (int j = 0; j < 4; j++) {
            float xv = vv[j];
            float a1 = fminf(fmaxf(rintf(xv*16.0f), -127.0f), 127.0f);
            float r1 = xv - a1*0.0625f;
            float a2 = fminf(fmaxf(rintf(r1*2048.0f), -127.0f), 127.0f);
            float r2 = r1 - a2*4.8828125e-4f;
            float a3 = fminf(fmaxf(rintf(r2*262144.0f), -127.0f), 127.0f);
            sh[0][w4+j][ci] = (int8_t)(int)a1;
            sh[1][w4+j][ci] = (int8_t)(int)a2;
            sh[2][w4+j][ci] = (int8_t)(int)a3;
        }
    }
    __syncthreads();
    size_t obase = (size_t)b*XPLANE + ((h+1)*PADW + 1)*CHAN + cihalf*128;
    for (int i = t; i < 3*56*8; i += 128) {    // 1344 uint4 units
        int p = i / 448;
        int rem = i - p*448;
        int w = rem >> 3;
        int u = rem & 7;
        uint4 d = *reinterpret_cast<const uint4*>(&sh[p][w][u*16]);
        *reinterpret_cast<uint4*>(&g_x8[(size_t)p*NXPAD + obase + w*CHAN + u*16]) = d;
    }
}

// ---------------- kernel 4: int8 implicit GEMM, 3-pass exact accumulation ---
__global__ __launch_bounds__(512, 1)
void k_conv(const float* __restrict__ alpha_p, float* __restrict__ out) {
    extern __shared__ char smem[];
    float* s_scale = (float*)(smem + STAGES*STG);
    float* s_bias  = s_scale + CHAN;

    int tid  = threadIdx.x;
    int warp = tid >> 5, lane = tid & 31;
    int wm = warp >> 2, wn = warp & 3;          // 4x4 warp grid; warp tile 32x32

    if (tid < CHAN) { s_scale[tid] = g_scale[tid]; s_bias[tid] = g_bias[tid]; }

    int m0 = blockIdx.x * BM;
    int n0 = blockIdx.y * BN;

    // loader geometry: rows tid>>3 and +64, 16B unit (tid&7)
    int lrow = tid >> 3;
    int lu16 = (tid & 7) * 16;
    size_t pixb[2];
    #pragma unroll
    for (int i = 0; i < 2; i++) {
        int gm = m0 + lrow + i*64;
        int b = gm / HWHW; int rem = gm - b*HWHW;
        int h = rem / WW;  int w = rem - h*WW;
        pixb[i] = (size_t)b*XPLANE + (h*PADW + w)*CHAN + lu16;
    }
    const int8_t* wb = g_w8 + (size_t)(n0 + lrow)*CHAN + lu16;   // + tap*CHAN*CHAN
    uint32_t sb   = smem_u32(smem);
    uint32_t adst = sb + (uint32_t)(lrow*RSTRIDE) + lu16;
    uint32_t bdst = adst + TILE_B;

    float acc_f[2][4][4];
    int   acc_i[2][4][4];
    #pragma unroll
    for (int mf = 0; mf < 2; mf++)
        #pragma unroll
        for (int nf = 0; nf < 4; nf++)
            #pragma unroll
            for (int j = 0; j < 4; j++) { acc_f[mf][nf][j] = 0.0f; acc_i[mf][nf][j] = 0; }

    auto fill = [&](int c) {
        int pass = c / 18;
        int cc   = c - pass*18;
        int tap  = cc >> 1;
        int ck   = cc & 1;
        int kh = tap / 3, kw = tap - kh*3;
        int st = c % STAGES;
        const int8_t* ap = g_x8 + (size_t)pass*NXPAD + (kh*PADW + kw)*CHAN + ck*128;
        uint32_t ad = adst + st*STG;
        asm volatile("cp.async.cg.shared.global [%0], [%1], 16;"
            :: "r"(ad), "l"(ap + pixb[0]));
        asm volatile("cp.async.cg.shared.global [%0], [%1], 16;"
            :: "r"(ad + 64*RSTRIDE), "l"(ap + pixb[1]));
        const int8_t* bp = wb + (size_t)tap*CHAN*CHAN + ck*128;
        uint32_t bd = bdst + st*STG;
        asm volatile("cp.async.cg.shared.global [%0], [%1], 16;"
            :: "r"(bd), "l"(bp));
        asm volatile("cp.async.cg.shared.global [%0], [%1], 16;"
            :: "r"(bd + 64*RSTRIDE), "l"(bp + 64*CHAN));
        asm volatile("cp.async.commit_group;");
    };

    fill(0); fill(1);

    const float pscale[3] = {0.0625f, 4.8828125e-4f, 3.814697265625e-6f};

    for (int c = 0; c < NCHUNK; c++) {
        asm volatile("cp.async.wait_group %0;" :: "n"(1));
        __syncthreads();
        if (c + 2 < NCHUNK) fill(c + 2);
        else asm volatile("cp.async.commit_group;");

        int st = c % STAGES;
        uint32_t Ab = sb + st*STG;
        uint32_t Bb = Ab + TILE_B;

        #pragma unroll
        for (int kk = 0; kk < 4; kk++) {
            uint32_t afr[2][4];
            uint32_t bfr[2][4];
            #pragma unroll
            for (int mf = 0; mf < 2; mf++) {
                int row = wm*32 + mf*16 + (lane & 15);
                uint32_t addr = Ab + row*RSTRIDE + kk*32 + ((lane >> 4) << 4);
                asm volatile("ldmatrix.sync.aligned.m8n8.x4.shared.b16 {%0,%1,%2,%3},[%4];"
                    : "=r"(afr[mf][0]), "=r"(afr[mf][1]), "=r"(afr[mf][2]), "=r"(afr[mf][3])
                    : "r"(addr));
            }
            #pragma unroll
            for (int np = 0; np < 2; np++) {
                int row = wn*32 + np*16 + (lane & 15);
                uint32_t addr = Bb + row*RSTRIDE + kk*32 + ((lane >> 4) << 4);
                asm volatile("ldmatrix.sync.aligned.m8n8.x4.shared.b16 {%0,%1,%2,%3},[%4];"
                    : "=r"(bfr[np][0]), "=r"(bfr[np][1]), "=r"(bfr[np][2]), "=r"(bfr[np][3])
                    : "r"(addr));
            }
            #pragma unroll
            for (int mf = 0; mf < 2; mf++)
                #pragma unroll
                for (int nf = 0; nf < 4; nf++)
                    asm volatile(
                        "mma.sync.aligned.m16n8k32.row.col.s32.s8.s8.s32 "
                        "{%0,%1,%2,%3},{%4,%5,%6,%7},{%8,%9},{%0,%1,%2,%3};"
                        : "+r"(acc_i[mf][nf][0]), "+r"(acc_i[mf][nf][1]),
                          "+r"(acc_i[mf][nf][2]), "+r"(acc_i[mf][nf][3])
                        : "r"(afr[mf][0]), "r"(afr[mf][1]), "r"(afr[mf][2]), "r"(afr[mf][3]),
                          "r"(bfr[nf>>1][nf&1]), "r"(bfr[nf>>1][2+(nf&1)]));
        }

        if ((c + 1) % 18 == 0) {               // end of a pass: fold exact s32 into f32
            float ps = pscale[c/18];
            #pragma unroll
            for (int mf = 0; mf < 2; mf++)
                #pragma unroll
                for (int nf = 0; nf < 4; nf++)
                    #pragma unroll
                    for (int j = 0; j < 4; j++) {
                        acc_f[mf][nf][j] = fmaf((float)acc_i[mf][nf][j], ps, acc_f[mf][nf][j]);
                        acc_i[mf][nf][j] = 0;
                    }
        }
    }

    // ---- epilogue: BN + PACT quantization ----
    float aval = alpha_p[0];
    float back = __fdiv_rn(aval, 15.0f);
    #pragma unroll
    for (int mf = 0; mf < 2; mf++) {
        #pragma unroll
        for (int jh = 0; jh < 2; jh++) {
            int rm  = m0 + wm*32 + mf*16 + (lane >> 2) + jh*8;
            int b2  = rm / HWHW;
            int hw2 = rm - b2*HWHW;
            float* obase = out + b2*CHAN*HWHW + hw2;
            #pragma unroll
            for (int nf = 0; nf < 4; nf++) {
                #pragma unroll
                for (int jl = 0; jl < 2; jl++) {
                    int j  = jh*2 + jl;
                    int oc = n0 + wn*32 + nf*8 + ((lane & 3) << 1) + jl;
                    float y = fmaf(acc_f[mf][nf][j], s_scale[oc], s_bias[oc]);
                    y = fminf(fmaxf(y, 0.0f), aval);
                    float q = rintf(__fdiv_rn(y * 15.0f, aval)) * back;
                    obase[oc * HWHW] = q;
                }
            }
        }
    }
}

// ---------------- launch ----------------------------------------------------
extern "C" void kernel_launch(void* const* d_in, const int* in_sizes, int n_in,
                              void* d_out, int out_size) {
    const float* x     = (const float*)d_in[0];
    const float* w     = (const float*)d_in[1];
    const float* gamma = (const float*)d_in[2];
    const float* beta  = (const float*)d_in[3];
    const float* mean  = (const float*)d_in[4];
    const float* var   = (const float*)d_in[5];
    const float* alpha = (const float*)d_in[6];
    float* out = (float*)d_out;

    static int init_done = 0;
    static void* tbits_ptr = 0;
    if (!init_done) {
        cudaFuncSetAttribute(k_conv, cudaFuncAttributeMaxDynamicSharedMemorySize, SMEM_REQ);
        cudaGetSymbolAddress(&tbits_ptr, g_Tbits);
        init_done = 1;
    }

    cudaMemsetAsync(tbits_ptr, 0, 4);          // re-zero the atomic-max cell
    k_max<<<256, 256>>>(w);
    k_prep_w<<<KDIM, 256>>>(w, gamma, beta, mean, var);
    k_convert<<<BATCH*HH*2, 128>>>(x);
    k_conv<<<dim3(MDIM/BM, CHAN/BN), 512, SMEM_REQ>>>(alpha, out);
}

// round 16
// speedup vs baseline: 3.0061x; 3.0061x over previous
#include <cuda_runtime.h>
#include <cuda_fp16.h>
#include <math.h>
#include <stdint.h>

// Problem constants
#define BATCH   32
#define CHAN    256
#define HH      56
#define WW      56
#define HWHW    3136
#define NWEIGHT (CHAN*CHAN*9)
#define KDIM    2304
#define MDIM    (BATCH*HWHW)            // 100352

// Padded NHWC activation layout
#define PADW    58
#define XPLANE  (PADW*PADW*CHAN)        // 861184
#define NXPAD   (BATCH*XPLANE)          // 27557888 halves per pass

// GEMM tiling: BM=128, BN=128, BK=64, 2 CTAs/SM
#define BM 128
#define BN 128
#define BK 64
#define NCHUNK 72                       // 2 passes * 9 taps * 4 ci-quarters
#define STAGES 3
#define AST 72                          // 64 + 8 pad halves (144B rows, LDSM conflict-free)
#define BST 136                         // 128 + 8 pad halves (272B rows, conflict-free)
#define A_BYTES (BM*AST*2)              // 18432
#define B_BYTES (BK*BST*2)              // 17408
#define STG     (A_BYTES + B_BYTES)     // 35840
#define SMEM_REQ (STAGES*STG + 2048)    // 109568  (2 CTAs fit in 228KB)

// ---------------- device scratch ----------------
__device__ __half g_xpad[2*NXPAD];          // padded NHWC hi/lo (~110 MB), borders stay 0
__device__ __half g_wmat[9*CHAN*CHAN];      // weights*15 as [tap][ci][oc]
__device__ float  g_scale[CHAN];
__device__ float  g_bias[CHAN];
__device__ unsigned g_Tbits;                // max |tanh(w)| as positive-float bits

__device__ __forceinline__ uint32_t smem_u32(const void* p) {
    return (uint32_t)__cvta_generic_to_shared(p);
}

// ---------------- kernel 1: max |tanh(w)| (parallel + atomicMax) ------------
__global__ __launch_bounds__(256)
void k_max(const float* __restrict__ w) {
    __shared__ float s[256];
    float m = 0.0f;
    for (int i = blockIdx.x*256 + threadIdx.x; i < NWEIGHT; i += 256*256) {
        float t = (float)tanh((double)w[i]);
        m = fmaxf(m, fabsf(t));
    }
    s[threadIdx.x] = m;
    __syncthreads();
    for (int o = 128; o > 0; o >>= 1) {
        if (threadIdx.x < o) s[threadIdx.x] = fmaxf(s[threadIdx.x], s[threadIdx.x+o]);
        __syncthreads();
    }
    if (threadIdx.x == 0) atomicMax(&g_Tbits, __float_as_uint(s[0]));
}

// ---------------- kernel 2: weight quantize [tap][ci][oc] + BN fold ---------
__global__ void k_prep_w(const float* __restrict__ w,
                         const float* __restrict__ gamma, const float* __restrict__ beta,
                         const float* __restrict__ mean,  const float* __restrict__ var) {
    int e = blockIdx.x*256 + threadIdx.x;      // grid KDIM x 256 == NWEIGHT
    float T = __uint_as_float(g_Tbits);
    float t  = (float)tanh((double)w[e]);
    float tq = __fdiv_rn(t, 2.0f*T) + 0.5f;
    float r  = rintf(tq * 15.0f);              // half-even, matches jnp.round
    int oc = e / KDIM;
    int rr = e - oc*KDIM;
    int ci = rr / 9;
    int tap = rr - ci*9;
    g_wmat[(tap*CHAN + ci)*CHAN + oc] = __float2half(2.0f*r - 15.0f);

    if (blockIdx.x == 0) {
        int c = threadIdx.x;
        float inv = __fdiv_rn(gamma[c], __fsqrt_rn(var[c] + 1e-5f));
        g_scale[c] = __fdiv_rn(inv, 15.0f);
        g_bias[c]  = fmaf(-mean[c], inv, beta[c]);
    }
}

// ---------------- kernel 3: NCHW fp32 -> padded NHWC fp16 hi/lo -------------
__global__ __launch_bounds__(128)
void k_convert(const float* __restrict__ x) {
    __shared__ __half sh[2][56][136];
    int bid = blockIdx.x;
    int cihalf = bid & 1;
    int bh = bid >> 1;
    int h = bh % HH;
    int b = bh / HH;
    int t = threadIdx.x;

    const float* xp = x + ((size_t)(b*CHAN + cihalf*128)*HH + h)*WW;
    #pragma unroll
    for (int i = 0; i < 14; i++) {
        int f = i*128 + t;
        int ci = f / 14;
        int c4 = f - ci*14;
        float4 v = *reinterpret_cast<const float4*>(xp + (size_t)ci*HWHW + c4*4);
        int w4 = c4*4;
        float vv[4] = {v.x, v.y, v.z, v.w};
        #pragma unroll
        for (int j = 0; j < 4; j++) {
            __half hh = __float2half(vv[j]);
            sh[0][w4+j][ci] = hh;
            sh[1][w4+j][ci] = __float2half(vv[j] - __half2float(hh));
        }
    }
    __syncthreads();
    int obase = b*XPLANE + ((h+1)*PADW + 1)*CHAN + cihalf*128;
    #pragma unroll
    for (int i = 0; i < 7; i++) {
        int u = i*128 + t;
        int w = u >> 4;
        int c16 = (u & 15)*8;
        uint4 dhi = *reinterpret_cast<const uint4*>(&sh[0][w][c16]);
        uint4 dlo = *reinterpret_cast<const uint4*>(&sh[1][w][c16]);
        int o = obase + w*CHAN + c16;
        *reinterpret_cast<uint4*>(&g_xpad[o])         = dhi;
        *reinterpret_cast<uint4*>(&g_xpad[NXPAD + o]) = dlo;
    }
}

// ---------------- kernel 4: implicit GEMM, 256 thr, 2 CTAs/SM ---------------
__global__ __launch_bounds__(256, 2)
void k_conv(const float* __restrict__ alpha_p, float* __restrict__ out) {
    extern __shared__ char smem[];
    float* s_scale = (float*)(smem + STAGES*STG);
    float* s_bias  = s_scale + CHAN;

    int tid  = threadIdx.x;
    int warp = tid >> 5, lane = tid & 31;
    int wm = warp >> 1, wn = warp & 1;          // 4x2 warp grid; warp tile 32x64

    int n0 = blockIdx.y * BN;
    if (tid < 128) {
        s_scale[tid] = g_scale[n0 + tid];
        s_bias[tid]  = g_bias[n0 + tid];
    }

    int m0 = blockIdx.x * BM;

    // A loader: row = tid>>1 (0..127), 4 x 16B units at (tid&1)*32 halves
    int arow = tid >> 1;
    int gm  = m0 + arow;
    int b   = gm / HWHW;  int rem = gm - b*HWHW;
    int h   = rem / WW;   int w   = rem - h*WW;
    const __half* abase = g_xpad + b*XPLANE + (h*PADW + w)*CHAN + (tid & 1)*32;
    uint32_t adst0 = smem_u32(smem) + (uint32_t)(arow*AST + (tid & 1)*32)*2;

    // B loader: 4 units: rows (tid>>4)+16j, unit col (tid&15)
    const __half* wbase = g_wmat + (tid >> 4)*CHAN + n0 + (tid & 15)*8;
    uint32_t bdst0 = smem_u32(smem) + (uint32_t)A_BYTES +
                     (uint32_t)((tid >> 4)*BST + (tid & 15)*8)*2;

    float acc[2][8][4];
    #pragma unroll
    for (int mf = 0; mf < 2; mf++)
        #pragma unroll
        for (int nf = 0; nf < 8; nf++)
            #pragma unroll
            for (int j = 0; j < 4; j++) acc[mf][nf][j] = 0.0f;

    auto fill = [&](int c) {
        int pass = (c >= 36) ? 1 : 0;
        int cc   = c - pass*36;
        int tap  = cc >> 2;
        int cq   = cc & 3;
        int kh = tap / 3, kw = tap - kh*3;
        int st = c % STAGES;
        const __half* asrc = abase + (long)pass*NXPAD + (kh*PADW + kw)*CHAN + cq*64;
        uint32_t ad = adst0 + st*STG;
        #pragma unroll
        for (int i = 0; i < 4; i++)                 // 4 x 16B: full 32 halves
            asm volatile("cp.async.cg.shared.global [%0], [%1], 16;"
                :: "r"(ad + i*16), "l"(asrc + i*8));
        const __half* bsrc = wbase + (tap*CHAN + cq*64)*CHAN;
        uint32_t bd = bdst0 + st*STG;
        #pragma unroll
        for (int j = 0; j < 4; j++)
            asm volatile("cp.async.cg.shared.global [%0], [%1], 16;"
                :: "r"(bd + (uint32_t)(j*16*BST)*2), "l"(bsrc + j*16*CHAN));
        asm volatile("cp.async.commit_group;");
    };

    fill(0); fill(1);

    for (int c = 0; c < NCHUNK; c++) {
        asm volatile("cp.async.wait_group %0;" :: "n"(1));
        __syncthreads();
        if (c + 2 < NCHUNK) fill(c + 2);
        else asm volatile("cp.async.commit_group;");

        int st = c % STAGES;
        const __half* Ab = (const __half*)(smem + st*STG);
        const __half* Bb = (const __half*)(smem + st*STG + A_BYTES);

        #pragma unroll
        for (int kk = 0; kk < 4; kk++) {
            uint32_t afr[2][4];
            uint32_t bfr[8][2];
            #pragma unroll
            for (int mf = 0; mf < 2; mf++) {
                int row = wm*32 + mf*16 + (lane & 15);
                int col = kk*16 + ((lane >> 4) << 3);
                uint32_t addr = smem_u32(&Ab[row*AST + col]);
                asm volatile("ldmatrix.sync.aligned.m8n8.x4.shared.b16 {%0,%1,%2,%3},[%4];"
                    : "=r"(afr[mf][0]), "=r"(afr[mf][1]), "=r"(afr[mf][2]), "=r"(afr[mf][3])
                    : "r"(addr));
            }
            #pragma unroll
            for (int bg = 0; bg < 4; bg++) {
                int row = kk*16 + (lane & 15);
                int col = wn*64 + bg*16 + ((lane >> 4) << 3);
                uint32_t addr = smem_u32(&Bb[row*BST + col]);
                asm volatile("ldmatrix.sync.aligned.m8n8.x4.trans.shared.b16 {%0,%1,%2,%3},[%4];"
                    : "=r"(bfr[bg*2][0]), "=r"(bfr[bg*2][1]),
                      "=r"(bfr[bg*2+1][0]), "=r"(bfr[bg*2+1][1])
                    : "r"(addr));
            }
            #pragma unroll
            for (int mf = 0; mf < 2; mf++)
                #pragma unroll
                for (int nf = 0; nf < 8; nf++)
                    asm volatile(
                        "mma.sync.aligned.m16n8k16.row.col.f32.f16.f16.f32 "
                        "{%0,%1,%2,%3},{%4,%5,%6,%7},{%8,%9},{%0,%1,%2,%3};"
                        : "+f"(acc[mf][nf][0]), "+f"(acc[mf][nf][1]),
                          "+f"(acc[mf][nf][2]), "+f"(acc[mf][nf][3])
                        : "r"(afr[mf][0]), "r"(afr[mf][1]), "r"(afr[mf][2]), "r"(afr[mf][3]),
                          "r"(bfr[nf][0]), "r"(bfr[nf][1]));
        }
    }

    // ---- epilogue: BN + PACT quantization ----
    float aval = alpha_p[0];
    float back = __fdiv_rn(aval, 15.0f);
    #pragma unroll
    for (int mf = 0; mf < 2; mf++) {
        #pragma unroll
        for (int jh = 0; jh < 2; jh++) {
            int rm  = m0 + wm*32 + mf*16 + (lane >> 2) + jh*8;
            int b2  = rm / HWHW;
            int hw2 = rm - b2*HWHW;
            float* obase = out + b2*CHAN*HWHW + hw2;
            #pragma unroll
            for (int nf = 0; nf < 8; nf++) {
                #pragma unroll
                for (int jl = 0; jl < 2; jl++) {
                    int j  = jh*2 + jl;
                    int lc = wn*64 + nf*8 + ((lane & 3) << 1) + jl;   // 0..127 local
                    float y = fmaf(acc[mf][nf][j], s_scale[lc], s_bias[lc]);
                    y = fminf(fmaxf(y, 0.0f), aval);
                    float q = rintf(__fdiv_rn(y * 15.0f, aval)) * back;
                    obase[(n0 + lc) * HWHW] = q;
                }
            }
        }
    }
}

// ---------------- launch ----------------------------------------------------
extern "C" void kernel_launch(void* const* d_in, const int* in_sizes, int n_in,
                              void* d_out, int out_size) {
    const float* x     = (const float*)d_in[0];
    const float* w     = (const float*)d_in[1];
    const float* gamma = (const float*)d_in[2];
    const float* beta  = (const float*)d_in[3];
    const float* mean  = (const float*)d_in[4];
    const float* var   = (const float*)d_in[5];
    const float* alpha = (const float*)d_in[6];
    float* out = (float*)d_out;

    static int init_done = 0;
    static void* tbits_ptr = 0;
    if (!init_done) {
        cudaFuncSetAttribute(k_conv, cudaFuncAttributeMaxDynamicSharedMemorySize, SMEM_REQ);
        cudaGetSymbolAddress(&tbits_ptr, g_Tbits);
        init_done = 1;
    }

    cudaMemsetAsync(tbits_ptr, 0, 4);          // re-zero the atomic-max cell
    k_max<<<256, 256>>>(w);
    k_prep_w<<<KDIM, 256>>>(w, gamma, beta, mean, var);
    k_convert<<<BATCH*HH*2, 128>>>(x);
    k_conv<<<dim3(MDIM/BM, CHAN/BN), 256, SMEM_REQ>>>(alpha, out);
}